// round 10
// baseline (speedup 1.0000x reference)
#include <cuda_runtime.h>
#include <math.h>

// Problem constants
#define M_TOT 32768            // 512*64 matrices
#define BLOCKS 512
#define THREADS 256
#define WPB 8
#define NWARPS (BLOCKS * WPB)  // 4096 warps -> 8 matrices each
#define TS 36                  // tile row stride in floats (16B-aligned, conflict-free)
#define TS4 9                  // tile row stride in float4
#define PSTRIDE 33             // stats entry stride
#define PART_ENTRIES (32 * PSTRIDE)   // 1056

// Scratch (static device arrays; no runtime allocation allowed)
__device__ float g_L[(size_t)M_TOT * 1024];        // Cholesky factors, ROW-major, lower chunks only
__device__ float g_part[PART_ENTRIES * BLOCKS];    // per-block partials, [entry][block]
__device__ float g_sums[PART_ENTRIES];
__device__ float g_stats[1025];                    // mean[32*32] (diag slot = logd mean) + factor

// ---------------------------------------------------------------------------
// Pass 1: predicated (lower-triangle) coalesced load of symmetric X with smem
// transpose, warp-per-matrix Cholesky with smem column broadcasts, row-major
// lower-triangle-only store of L, Log-Cholesky statistics accumulation.
// ---------------------------------------------------------------------------
__global__ void __launch_bounds__(THREADS) chol_pass1(const float* __restrict__ X) {
    __shared__ float4 sbuf[WPB * 304];   // per warp: 288 tile f4 + 16 colbuf f4
    const int lane = threadIdx.x & 31;
    const int wl   = threadIdx.x >> 5;
    float4* tile = sbuf + wl * 304;
    float*  colf = (float*)(tile + 288);
    const int gw = blockIdx.x * WPB + wl;

    float acc[32];
#pragma unroll
    for (int j = 0; j < 32; j++) acc[j] = 0.f;
    float accsq = 0.f;

    for (int m = gw; m < M_TOT; m += NWARPS) {
        // predicated coalesced load: only chunks intersecting the lower triangle.
        const float4* xs = (const float4*)(X + (size_t)m * 1024);
        const int row  = 4 * ((int)lane >> 3);        // base row handled by this lane per q... recomputed below
#pragma unroll
        for (int q = 0; q < 8; q++) {
            int r = 4 * q + (lane >> 3);
            int cc = lane & 7;                        // chunk covers cols 4cc..4cc+3
            float4 v = make_float4(0.f, 0.f, 0.f, 0.f);
            if (4 * cc <= r) v = xs[q * 32 + lane];
            tile[r * TS4 + cc] = v;
        }
        (void)row;
        __syncwarp();
        // own row into registers (upper entries are zero)
        float a[32];
#pragma unroll
        for (int q = 0; q < 8; q++) {
            float4 v = tile[lane * TS4 + q];
            a[4*q+0] = v.x; a[4*q+1] = v.y; a[4*q+2] = v.z; a[4*q+3] = v.w;
        }

        float mydiag = 1.f;
#pragma unroll
        for (int k = 0; k < 32; k++) {
            float akk  = __shfl_sync(0xffffffffu, a[k], k);
            float rinv = rsqrtf(akk);
            float lik  = a[k] * rinv;           // lane==k -> sqrt(akk)
            if (lane < k) lik = 0.f;
            if (lane == k) mydiag = lik;
            a[k] = lik;
            float* cb = colf + ((k & 1) << 5);  // double-buffered column broadcast
            cb[lane] = lik;
            __syncwarp();
#pragma unroll
            for (int q = (k + 1) / 4; q < 8; q++) {
                float4 c = ((const float4*)cb)[q];
                if (4*q+0 > k) a[4*q+0] -= lik * c.x;
                if (4*q+1 > k) a[4*q+1] -= lik * c.y;
                if (4*q+2 > k) a[4*q+2] -= lik * c.z;
                if (4*q+3 > k) a[4*q+3] -= lik * c.w;
            }
        }
        float logd = __logf(mydiag);

        // stage L row-major and store only lower-triangle chunks (coalesced .128)
#pragma unroll
        for (int q = 0; q < 8; q++)
            tile[lane * TS4 + q] = make_float4(a[4*q], a[4*q+1], a[4*q+2], a[4*q+3]);
        __syncwarp();
        float4* gl4 = (float4*)(g_L + (size_t)m * 1024);
#pragma unroll
        for (int q = 0; q < 8; q++) {
            int r = 4 * q + (lane >> 3);
            int cc = lane & 7;
            if (4 * cc <= r) gl4[q * 32 + lane] = tile[r * TS4 + cc];
        }
        __syncwarp();

        // accumulate Log-Cholesky coords (strict lower + logd in diag slot)
#pragma unroll
        for (int j = 0; j < 32; j++) {
            float v = (j < lane) ? a[j] : ((j == lane) ? logd : 0.f);
            acc[j] += v;
            accsq  += v * v;
        }
    }

    // block reduction: reuse sbuf as sred (tiles dead now)
    __syncthreads();
    float* sred = (float*)sbuf;
#pragma unroll
    for (int j = 0; j < 32; j++)
        sred[wl * PART_ENTRIES + lane * PSTRIDE + j] = acc[j];
    sred[wl * PART_ENTRIES + lane * PSTRIDE + 32] = accsq;
    __syncthreads();

    for (int e = threadIdx.x; e < PART_ENTRIES; e += THREADS) {
        float s = 0.f;
#pragma unroll
        for (int w = 0; w < WPB; w++) s += sred[w * PART_ENTRIES + e];
        g_part[e * BLOCKS + blockIdx.x] = s;
    }
}

// ---------------------------------------------------------------------------
// k2a: deterministic tree reduction of 512 block partials per entry (coalesced).
// ---------------------------------------------------------------------------
__global__ void reduce2a() {
    __shared__ float red[BLOCKS];
    const int e = blockIdx.x;
    red[threadIdx.x] = g_part[e * BLOCKS + threadIdx.x];
    __syncthreads();
#pragma unroll
    for (int s = BLOCKS / 2; s > 0; s >>= 1) {
        if ((int)threadIdx.x < s) red[threadIdx.x] += red[threadIdx.x + s];
        __syncthreads();
    }
    if (threadIdx.x == 0) g_sums[e] = red[0];
}

// ---------------------------------------------------------------------------
// k2b: means, variance = E||x||^2 - ||Ex||^2, factor = s / sqrt(var).
// ---------------------------------------------------------------------------
__global__ void stats_pass(const float* __restrict__ s_in) {
    __shared__ float red[1024];
    const int t = threadIdx.x;               // 1024 threads
    const int i = t >> 5, j = t & 31;
    const float invM = 1.0f / (float)M_TOT;

    float mean = g_sums[i * PSTRIDE + j] * invM;   // 0 for strictly-upper slots
    g_stats[i * 32 + j] = mean;
    float val = -mean * mean;
    if (t < 32) val += g_sums[t * PSTRIDE + 32] * invM;
    red[t] = val;
    __syncthreads();
#pragma unroll
    for (int s = 512; s > 0; s >>= 1) {
        if (t < s) red[t] += red[t + s];
        __syncthreads();
    }
    if (t == 0) {
        float var = red[0];
        g_stats[1024] = s_in[0] / sqrtf(var);
    }
}

// ---------------------------------------------------------------------------
// Pass 3: predicated coalesced load of row-major L into row-major smem tile,
// vectorized b/mean row loads, center + geodesic rescale, j-outer syrk with
// float4 row broadcasts, coalesced store of the SPD output through smem.
// ---------------------------------------------------------------------------
__global__ void __launch_bounds__(THREADS, 3) out_pass(float* __restrict__ out) {
    __shared__ float4 sbuf[WPB * 288];       // 36.9 KB tiles
    __shared__ float4 smean4[32 * TS4];      // padded mean rows (float4 view)
    __shared__ float  sfac;

    {   // build padded mean (stride 36 floats), zero the pad
        float* smean = (float*)smean4;
        for (int e = threadIdx.x; e < 32 * TS; e += THREADS) smean[e] = 0.f;
        __syncthreads();
        for (int e = threadIdx.x; e < 1024; e += THREADS)
            smean[(e >> 5) * TS + (e & 31)] = g_stats[e];
        if (threadIdx.x == 0) sfac = g_stats[1024];
    }
    __syncthreads();
    const float factor = sfac;

    const int lane = threadIdx.x & 31;
    const int wl   = threadIdx.x >> 5;
    float4* tile = sbuf + wl * 288;
    const int gw = blockIdx.x * WPB + wl;

    for (int m = gw; m < M_TOT; m += NWARPS) {
        // predicated coalesced load of row-major L (upper chunks stale; masked later)
        const float4* ls = (const float4*)(g_L + (size_t)m * 1024);
#pragma unroll
        for (int q = 0; q < 8; q++) {
            int r = 4 * q + (lane >> 3);
            int cc = lane & 7;
            if (4 * cc <= r) tile[r * TS4 + cc] = ls[q * 32 + lane];
        }
        __syncwarp();

        // own L row + own mean row (vectorized, conflict-free: stride 9 f4)
        float b[32];
        float dlog = 0.f, mdiag = 0.f;
#pragma unroll
        for (int q = 0; q < 8; q++) {
            float4 va = tile[lane * TS4 + q];
            float4 vm = smean4[lane * TS4 + q];
            float av[4] = {va.x, va.y, va.z, va.w};
            float mv[4] = {vm.x, vm.y, vm.z, vm.w};
#pragma unroll
            for (int t = 0; t < 4; t++) {
                int j = 4 * q + t;
                float v = factor * (av[t] - mv[t]);
                b[j] = (j < lane) ? v : 0.f;
                if (j == lane) { dlog = __logf(av[t]); mdiag = mv[t]; }
            }
        }
#pragma unroll
        for (int j = 0; j < 32; j++)
            if (j == lane) b[j] = __expf(factor * (dlog - mdiag));

        // write b row back (full row incl. zeros -> unpredicated syrk)
#pragma unroll
        for (int q = 0; q < 8; q++)
            tile[lane * TS4 + q] = make_float4(b[4*q], b[4*q+1], b[4*q+2], b[4*q+3]);
        __syncwarp();

        // X_out row i: o[j] = sum_{k<=j} b_i[k] * b_j[k]; j outer, row-chunk
        // broadcasts (tile zeros beyond j make FMAs unpredicated-safe).
        float o[32];
#pragma unroll
        for (int j = 0; j < 32; j++) {
            float s = 0.f;
#pragma unroll
            for (int q = 0; q <= j / 4; q++) {
                float4 c = tile[j * TS4 + q];        // b_j[4q..4q+3], broadcast
                s += b[4*q+0] * c.x + b[4*q+1] * c.y + b[4*q+2] * c.z + b[4*q+3] * c.w;
            }
            o[j] = s;
        }
        __syncwarp();   // all tile reads done before restage

        // stage o row-major, then coalesced store (full matrix)
#pragma unroll
        for (int q = 0; q < 8; q++)
            tile[lane * TS4 + q] = make_float4(o[4*q], o[4*q+1], o[4*q+2], o[4*q+3]);
        __syncwarp();
        float4* od = (float4*)(out + (size_t)m * 1024);
#pragma unroll
        for (int q = 0; q < 8; q++)
            od[q * 32 + lane] = tile[(4 * q + (lane >> 3)) * TS4 + (lane & 7)];
        __syncwarp();
    }
}

extern "C" void kernel_launch(void* const* d_in, const int* in_sizes, int n_in,
                              void* d_out, int out_size) {
    const float* X = (const float*)d_in[0];
    const float* s = (const float*)d_in[1];
    float* out = (float*)d_out;

    chol_pass1<<<BLOCKS, THREADS>>>(X);
    reduce2a<<<PART_ENTRIES, BLOCKS>>>();
    stats_pass<<<1, 1024>>>(s);
    out_pass<<<BLOCKS, THREADS>>>(out);
}

// round 11
// speedup vs baseline: 1.0341x; 1.0341x over previous
#include <cuda_runtime.h>
#include <math.h>

// Problem constants
#define M_TOT 32768            // 512*64 matrices
#define BLOCKS 512
#define THREADS 256
#define WPB 8
#define NWARPS (BLOCKS * WPB)  // 4096 warps -> 8 matrices each
#define TS 36                  // tile row stride in floats (16B-aligned, conflict-free)
#define TS4 9                  // tile row stride in float4
#define PSTRIDE 33             // stats entry stride
#define PART_ENTRIES (32 * PSTRIDE)   // 1056

// Scratch (static device arrays; no runtime allocation allowed)
__device__ float g_L[(size_t)M_TOT * 1024];        // Cholesky factors, ROW-major (upper zeros)
__device__ float g_part[PART_ENTRIES * BLOCKS];    // per-block partials, [entry][block]
__device__ float g_sums[PART_ENTRIES];
__device__ float g_stats[1025];                    // mean[32*32] (diag slot = logd mean) + factor

// ---------------------------------------------------------------------------
// Pass 1: coalesced load + smem transpose, warp-per-matrix Cholesky with
// smem column broadcasts (R9-identical loop), staged row-major full store of
// L (8x STG.128), Log-Cholesky statistics accumulation.
// ---------------------------------------------------------------------------
__global__ void __launch_bounds__(THREADS) chol_pass1(const float* __restrict__ X) {
    __shared__ float4 sbuf[WPB * 304];   // per warp: 288 tile f4 + 16 colbuf f4
    const int lane = threadIdx.x & 31;
    const int wl   = threadIdx.x >> 5;
    float4* tile = sbuf + wl * 304;
    float*  colf = (float*)(tile + 288);
    const int gw = blockIdx.x * WPB + wl;

    float acc[32];
#pragma unroll
    for (int j = 0; j < 32; j++) acc[j] = 0.f;
    float accsq = 0.f;

    for (int m = gw; m < M_TOT; m += NWARPS) {
        // coalesced load of X, transpose through smem (row-major tile)
        const float4* xs = (const float4*)(X + (size_t)m * 1024);
#pragma unroll
        for (int q = 0; q < 8; q++) {
            float4 v = xs[q * 32 + lane];
            tile[(4 * q + (lane >> 3)) * TS4 + (lane & 7)] = v;
        }
        __syncwarp();
        // own row into registers
        float a[32];
#pragma unroll
        for (int q = 0; q < 8; q++) {
            float4 v = tile[lane * TS4 + q];
            a[4*q+0] = v.x; a[4*q+1] = v.y; a[4*q+2] = v.z; a[4*q+3] = v.w;
        }

        float mydiag = 1.f;
#pragma unroll
        for (int k = 0; k < 32; k++) {
            float akk  = __shfl_sync(0xffffffffu, a[k], k);
            float rinv = rsqrtf(akk);
            float lik  = a[k] * rinv;           // lane==k -> sqrt(akk)
            if (lane < k) lik = 0.f;
            if (lane == k) mydiag = lik;
            a[k] = lik;
            float* cb = colf + ((k & 1) << 5);  // double-buffered column broadcast
            cb[lane] = lik;
            __syncwarp();
#pragma unroll
            for (int q = (k + 1) / 4; q < 8; q++) {
                float4 c = ((const float4*)cb)[q];
                if (4*q+0 > k) a[4*q+0] -= lik * c.x;
                if (4*q+1 > k) a[4*q+1] -= lik * c.y;
                if (4*q+2 > k) a[4*q+2] -= lik * c.z;
                if (4*q+3 > k) a[4*q+3] -= lik * c.w;
            }
        }
        float logd = __logf(mydiag);

        // stage L row-major (upper already zero) and store coalesced .128
#pragma unroll
        for (int q = 0; q < 8; q++)
            tile[lane * TS4 + q] = make_float4(a[4*q], a[4*q+1], a[4*q+2], a[4*q+3]);
        __syncwarp();
        float4* gl4 = (float4*)(g_L + (size_t)m * 1024);
#pragma unroll
        for (int q = 0; q < 8; q++)
            gl4[q * 32 + lane] = tile[(4 * q + (lane >> 3)) * TS4 + (lane & 7)];
        __syncwarp();

        // accumulate Log-Cholesky coords (strict lower + logd in diag slot)
#pragma unroll
        for (int j = 0; j < 32; j++) {
            float v = (j < lane) ? a[j] : ((j == lane) ? logd : 0.f);
            acc[j] += v;
            accsq  += v * v;
        }
    }

    // block reduction: reuse sbuf as sred (tiles dead now)
    __syncthreads();
    float* sred = (float*)sbuf;
#pragma unroll
    for (int j = 0; j < 32; j++)
        sred[wl * PART_ENTRIES + lane * PSTRIDE + j] = acc[j];
    sred[wl * PART_ENTRIES + lane * PSTRIDE + 32] = accsq;
    __syncthreads();

    for (int e = threadIdx.x; e < PART_ENTRIES; e += THREADS) {
        float s = 0.f;
#pragma unroll
        for (int w = 0; w < WPB; w++) s += sred[w * PART_ENTRIES + e];
        g_part[e * BLOCKS + blockIdx.x] = s;
    }
}

// ---------------------------------------------------------------------------
// k2a: deterministic tree reduction of 512 block partials per entry (coalesced).
// ---------------------------------------------------------------------------
__global__ void reduce2a() {
    __shared__ float red[BLOCKS];
    const int e = blockIdx.x;
    red[threadIdx.x] = g_part[e * BLOCKS + threadIdx.x];
    __syncthreads();
#pragma unroll
    for (int s = BLOCKS / 2; s > 0; s >>= 1) {
        if ((int)threadIdx.x < s) red[threadIdx.x] += red[threadIdx.x + s];
        __syncthreads();
    }
    if (threadIdx.x == 0) g_sums[e] = red[0];
}

// ---------------------------------------------------------------------------
// k2b: means, variance = E||x||^2 - ||Ex||^2, factor = s / sqrt(var).
// ---------------------------------------------------------------------------
__global__ void stats_pass(const float* __restrict__ s_in) {
    __shared__ float red[1024];
    const int t = threadIdx.x;               // 1024 threads
    const int i = t >> 5, j = t & 31;
    const float invM = 1.0f / (float)M_TOT;

    float mean = g_sums[i * PSTRIDE + j] * invM;   // 0 for strictly-upper slots
    g_stats[i * 32 + j] = mean;
    float val = -mean * mean;
    if (t < 32) val += g_sums[t * PSTRIDE + 32] * invM;
    red[t] = val;
    __syncthreads();
#pragma unroll
    for (int s = 512; s > 0; s >>= 1) {
        if (t < s) red[t] += red[t + s];
        __syncthreads();
    }
    if (t == 0) {
        float var = red[0];
        g_stats[1024] = s_in[0] / sqrtf(var);
    }
}

// ---------------------------------------------------------------------------
// Pass 3: coalesced load of row-major L -> row-major tile, vectorized own-row
// and mean-row reads (8+8 LDS.128), b in registers with a single diag select,
// triangular j-outer syrk with float4 row broadcasts (compile-time bounds),
// coalesced store through smem staging.
// ---------------------------------------------------------------------------
__global__ void __launch_bounds__(THREADS, 3) out_pass(float* __restrict__ out) {
    __shared__ float4 sbuf[WPB * 288];       // 36.9 KB tiles
    __shared__ float4 smean4[32 * TS4];      // padded mean rows (float4 view)
    __shared__ float  sfac;

    {   // build padded mean (stride 36 floats), zero the pad
        float* smean = (float*)smean4;
        for (int e = threadIdx.x; e < 32 * TS; e += THREADS) smean[e] = 0.f;
        __syncthreads();
        for (int e = threadIdx.x; e < 1024; e += THREADS)
            smean[(e >> 5) * TS + (e & 31)] = g_stats[e];
        if (threadIdx.x == 0) sfac = g_stats[1024];
    }
    __syncthreads();
    const float factor = sfac;

    const int lane = threadIdx.x & 31;
    const int wl   = threadIdx.x >> 5;
    float4* tile = sbuf + wl * 288;
    float*  tf   = (float*)tile;
    const float* smean = (const float*)smean4;
    const int gw = blockIdx.x * WPB + wl;

    for (int m = gw; m < M_TOT; m += NWARPS) {
        // coalesced load of row-major L into row-major tile
        const float4* ls = (const float4*)(g_L + (size_t)m * 1024);
#pragma unroll
        for (int q = 0; q < 8; q++) {
            float4 v = ls[q * 32 + lane];
            tile[(4 * q + (lane >> 3)) * TS4 + (lane & 7)] = v;
        }
        __syncwarp();

        // diag pieces (2 conflict-free scalar LDS: addr stride 37 -> distinct banks)
        float dL    = tf[lane * TS + lane];
        float mdiag = smean[lane * TS + lane];
        float edc   = __expf(factor * (__logf(dL) - mdiag));

        // own row b: zeros above diagonal fall out automatically (L upper = 0,
        // mean strict-upper = 0); only the diagonal needs a select.
        float b[32];
#pragma unroll
        for (int q = 0; q < 8; q++) {
            float4 va = tile[lane * TS4 + q];
            float4 vm = smean4[lane * TS4 + q];
            b[4*q+0] = factor * (va.x - vm.x);
            b[4*q+1] = factor * (va.y - vm.y);
            b[4*q+2] = factor * (va.z - vm.z);
            b[4*q+3] = factor * (va.w - vm.w);
        }
#pragma unroll
        for (int j = 0; j < 32; j++)
            if (j == lane) b[j] = edc;

        // write b row back (full row incl. zeros)
#pragma unroll
        for (int q = 0; q < 8; q++)
            tile[lane * TS4 + q] = make_float4(b[4*q], b[4*q+1], b[4*q+2], b[4*q+3]);
        __syncwarp();

        // X_out row i: o[j] = sum_{k<=j} b_i[k] * b_j[k]; j outer, broadcast
        // row-chunk reads; compile-time triangular bound, no runtime predicates.
        float o[32];
#pragma unroll
        for (int j = 0; j < 32; j++) {
            float s = 0.f;
#pragma unroll
            for (int q = 0; q <= j / 4; q++) {
                float4 c = tile[j * TS4 + q];        // b_j[4q..4q+3], broadcast
                s += b[4*q+0] * c.x + b[4*q+1] * c.y + b[4*q+2] * c.z + b[4*q+3] * c.w;
            }
            o[j] = s;
        }
        __syncwarp();   // all tile reads done before restage

        // stage o row-major, then coalesced store
#pragma unroll
        for (int q = 0; q < 8; q++)
            tile[lane * TS4 + q] = make_float4(o[4*q], o[4*q+1], o[4*q+2], o[4*q+3]);
        __syncwarp();
        float4* od = (float4*)(out + (size_t)m * 1024);
#pragma unroll
        for (int q = 0; q < 8; q++)
            od[q * 32 + lane] = tile[(4 * q + (lane >> 3)) * TS4 + (lane & 7)];
        __syncwarp();
    }
}

extern "C" void kernel_launch(void* const* d_in, const int* in_sizes, int n_in,
                              void* d_out, int out_size) {
    const float* X = (const float*)d_in[0];
    const float* s = (const float*)d_in[1];
    float* out = (float*)d_out;

    chol_pass1<<<BLOCKS, THREADS>>>(X);
    reduce2a<<<PART_ENTRIES, BLOCKS>>>();
    stats_pass<<<1, 1024>>>(s);
    out_pass<<<BLOCKS, THREADS>>>(out);
}

// round 12
// speedup vs baseline: 1.3564x; 1.3116x over previous
#include <cuda_runtime.h>
#include <math.h>

// Problem constants
#define M_TOT 32768            // 512*64 matrices
#define BLOCKS 1024
#define THREADS 128
#define WPB 4
#define NWARPS (BLOCKS * WPB)  // 4096 warps -> 8 matrices each
#define TS 36                  // tile row stride in floats (16B-aligned, conflict-free)
#define TS4 9                  // tile row stride in float4
#define PSTRIDE 33             // stats entry stride
#define PART_ENTRIES (32 * PSTRIDE)   // 1056

// Scratch (static device arrays; no runtime allocation allowed)
__device__ float g_L[(size_t)M_TOT * 1024];        // Cholesky factors, COLUMN-major per matrix
__device__ float g_part[PART_ENTRIES * BLOCKS];    // per-block partials, [entry][block]
__device__ float g_sums[PART_ENTRIES];
__device__ float g_stats[1025];                    // mean[32*32] (diag slot = logd mean) + factor

// ---------------------------------------------------------------------------
// Pass 1: coalesced load + smem transpose, warp-per-matrix Cholesky with
// shared-memory column broadcasts (float4), direct coalesced column-major
// store of L (in-loop, overlapped), Log-Cholesky statistic accumulation.
// ---------------------------------------------------------------------------
__global__ void __launch_bounds__(THREADS) chol_pass1(const float* __restrict__ X) {
    __shared__ float4 sbuf[WPB * 304];   // per warp: 288 tile f4 + 16 colbuf f4
    const int lane = threadIdx.x & 31;
    const int wl   = threadIdx.x >> 5;
    float4* tile = sbuf + wl * 304;
    float*  colf = (float*)(tile + 288);
    const int gw = blockIdx.x * WPB + wl;

    float acc[32];
#pragma unroll
    for (int j = 0; j < 32; j++) acc[j] = 0.f;
    float accsq = 0.f;

    for (int m = gw; m < M_TOT; m += NWARPS) {
        // coalesced load of X, transpose through smem (row-major tile)
        const float4* xs = (const float4*)(X + (size_t)m * 1024);
#pragma unroll
        for (int q = 0; q < 8; q++) {
            float4 v = xs[q * 32 + lane];
            tile[(4 * q + (lane >> 3)) * TS4 + (lane & 7)] = v;
        }
        __syncwarp();
        // own row into registers (conflict-free LDS.128)
        float a[32];
#pragma unroll
        for (int q = 0; q < 8; q++) {
            float4 v = tile[lane * TS4 + q];
            a[4*q+0] = v.x; a[4*q+1] = v.y; a[4*q+2] = v.z; a[4*q+3] = v.w;
        }

        float* gl = g_L + (size_t)m * 1024;
        float mydiag = 1.f;
#pragma unroll
        for (int k = 0; k < 32; k++) {
            float akk  = __shfl_sync(0xffffffffu, a[k], k);
            float rinv = rsqrtf(akk);
            float lik  = a[k] * rinv;           // lane==k -> sqrt(akk)
            if (lane < k) lik = 0.f;
            if (lane == k) mydiag = lik;
            a[k] = lik;
            gl[k * 32 + lane] = lik;            // coalesced column-major store of L
            float* cb = colf + ((k & 1) << 5);  // double-buffered column broadcast
            cb[lane] = lik;
            __syncwarp();
            // rank-1 update via broadcast float4 reads of column k
#pragma unroll
            for (int q = (k + 1) / 4; q < 8; q++) {
                float4 c = ((const float4*)cb)[q];
                if (4*q+0 > k) a[4*q+0] -= lik * c.x;
                if (4*q+1 > k) a[4*q+1] -= lik * c.y;
                if (4*q+2 > k) a[4*q+2] -= lik * c.z;
                if (4*q+3 > k) a[4*q+3] -= lik * c.w;
            }
        }
        float logd = __logf(mydiag);

        // accumulate Log-Cholesky coords (strict lower + logd in diag slot)
#pragma unroll
        for (int j = 0; j < 32; j++) {
            float v = (j < lane) ? a[j] : ((j == lane) ? logd : 0.f);
            acc[j] += v;
            accsq  += v * v;
        }
    }

    // block reduction: reuse sbuf as sred (tiles dead now)
    __syncthreads();
    float* sred = (float*)sbuf;   // WPB*PART_ENTRIES floats fits in sbuf
#pragma unroll
    for (int j = 0; j < 32; j++)
        sred[wl * PART_ENTRIES + lane * PSTRIDE + j] = acc[j];
    sred[wl * PART_ENTRIES + lane * PSTRIDE + 32] = accsq;
    __syncthreads();

    for (int e = threadIdx.x; e < PART_ENTRIES; e += THREADS) {
        float s = 0.f;
#pragma unroll
        for (int w = 0; w < WPB; w++) s += sred[w * PART_ENTRIES + e];
        g_part[e * BLOCKS + blockIdx.x] = s;   // [entry][block] -> coalesced reduce
    }
}

// ---------------------------------------------------------------------------
// k2a: deterministic tree reduction of 1024 block partials per entry (coalesced).
// ---------------------------------------------------------------------------
__global__ void reduce2a() {
    __shared__ float red[BLOCKS];
    const int e = blockIdx.x;
    red[threadIdx.x] = g_part[e * BLOCKS + threadIdx.x];
    __syncthreads();
#pragma unroll
    for (int s = BLOCKS / 2; s > 0; s >>= 1) {
        if ((int)threadIdx.x < s) red[threadIdx.x] += red[threadIdx.x + s];
        __syncthreads();
    }
    if (threadIdx.x == 0) g_sums[e] = red[0];
}

// ---------------------------------------------------------------------------
// k2b: means, variance = E||x||^2 - ||Ex||^2, factor = s / sqrt(var).
// ---------------------------------------------------------------------------
__global__ void stats_pass(const float* __restrict__ s_in) {
    __shared__ float red[1024];
    const int t = threadIdx.x;               // 1024 threads
    const int i = t >> 5, j = t & 31;
    const float invM = 1.0f / (float)M_TOT;

    float mean = g_sums[i * PSTRIDE + j] * invM;   // 0 for strictly-upper slots
    g_stats[i * 32 + j] = mean;
    float val = -mean * mean;
    if (t < 32) val += g_sums[t * PSTRIDE + 32] * invM;
    red[t] = val;
    __syncthreads();
#pragma unroll
    for (int s = 512; s > 0; s >>= 1) {
        if (t < s) red[t] += red[t + s];
        __syncthreads();
    }
    if (t == 0) {
        float var = red[0];
        g_stats[1024] = s_in[0] / sqrtf(var);
    }
}

// ---------------------------------------------------------------------------
// Pass 3: coalesced column-major load of L into smem, center + geodesic
// rescale, L_out L_out^T with float4 broadcast reads (k outer, j vectorized),
// coalesced store of the SPD output through smem staging. Natural register
// allocation (no min-blocks cap -> no spills); occupancy comes from the
// 128-thread block granularity.
// ---------------------------------------------------------------------------
__global__ void __launch_bounds__(THREADS) out_pass(float* __restrict__ out) {
    __shared__ float4 sbuf[WPB * 288];       // tiles
    __shared__ float  smean[32 * TS];        // padded mean (stride 36)
    __shared__ float  sfac;

    for (int e = threadIdx.x; e < 1024; e += THREADS)
        smean[(e >> 5) * TS + (e & 31)] = g_stats[e];
    if (threadIdx.x == 0) sfac = g_stats[1024];
    __syncthreads();
    const float factor = sfac;

    const int lane = threadIdx.x & 31;
    const int wl   = threadIdx.x >> 5;
    float4* tile = sbuf + wl * 288;
    float*  tf   = (float*)tile;
    const int gw = blockIdx.x * WPB + wl;

    for (int m = gw; m < M_TOT; m += NWARPS) {
        // coalesced load of column-major L -> column-major smem tile tf[col*TS + row]
        const float4* ls = (const float4*)(g_L + (size_t)m * 1024);
#pragma unroll
        for (int q = 0; q < 8; q++) {
            float4 v = ls[q * 32 + lane];    // col 4q+lane/8, rows 4(lane&7)..+3
            tile[(4 * q + (lane >> 3)) * TS4 + (lane & 7)] = v;
        }
        __syncwarp();

        // centered / rescaled own row b (lane i = row i). Upper entries are 0
        // automatically (L upper zeros, mean strict-upper zeros).
        float dL    = tf[lane * TS + lane];          // L[i][i]
        float mdiag = smean[lane * TS + lane];       // logd mean
        float edc   = __expf(factor * (__logf(dL) - mdiag));
        float b[32];
#pragma unroll
        for (int j = 0; j < 32; j++) {
            float aj = tf[j * TS + lane];            // L[i][j]  (conflict-free)
            float mj = smean[lane * TS + j];
            float v  = factor * (aj - mj);
            b[j] = (j == lane) ? edc : v;
        }
        // write b back into own column-major slots (only lane i touches (j,i))
#pragma unroll
        for (int j = 0; j < 32; j++) tf[j * TS + lane] = b[j];
        __syncwarp();

        // X_out row i: o[j] = sum_k b_i[k] * b_j[k]; k outer, j chunks of 4
        // (broadcast LDS.128 of column k = {b_j[k]}_j). b[k]=0 for k>lane
        // truncates the row; tile zeros truncate j<k.
        float o[32];
#pragma unroll
        for (int j = 0; j < 32; j++) o[j] = 0.f;
#pragma unroll
        for (int k = 0; k < 32; k++) {
            float bk = b[k];
#pragma unroll
            for (int q = k / 4; q < 8; q++) {
                float4 c = tile[k * TS4 + q];        // b_{4q..4q+3}[k], broadcast
                if (4*q+0 >= k) o[4*q+0] += bk * c.x;
                if (4*q+1 >= k) o[4*q+1] += bk * c.y;
                if (4*q+2 >= k) o[4*q+2] += bk * c.z;
                if (4*q+3 >= k) o[4*q+3] += bk * c.w;
            }
        }
        __syncwarp();   // all tile reads done before restage

        // stage o row-major, then coalesced store
#pragma unroll
        for (int q = 0; q < 8; q++)
            tile[lane * TS4 + q] = make_float4(o[4*q], o[4*q+1], o[4*q+2], o[4*q+3]);
        __syncwarp();
        float4* od = (float4*)(out + (size_t)m * 1024);
#pragma unroll
        for (int q = 0; q < 8; q++)
            od[q * 32 + lane] = tile[(4 * q + (lane >> 3)) * TS4 + (lane & 7)];
        __syncwarp();
    }
}

extern "C" void kernel_launch(void* const* d_in, const int* in_sizes, int n_in,
                              void* d_out, int out_size) {
    const float* X = (const float*)d_in[0];
    const float* s = (const float*)d_in[1];
    float* out = (float*)d_out;

    chol_pass1<<<BLOCKS, THREADS>>>(X);
    reduce2a<<<PART_ENTRIES, BLOCKS>>>();
    stats_pass<<<1, 1024>>>(s);
    out_pass<<<BLOCKS, THREADS>>>(out);
}

// round 13
// speedup vs baseline: 1.3995x; 1.0318x over previous
#include <cuda_runtime.h>
#include <math.h>

// Problem constants
#define M_TOT 32768            // 512*64 matrices
#define BLOCKS 1024
#define THREADS 128
#define WPB 4
#define NWARPS (BLOCKS * WPB)  // 4096 warps -> 8 matrices each
#define TS 36                  // tile row stride in floats (16B-aligned, conflict-free)
#define TS4 9                  // tile row stride in float4
#define PSTRIDE 33             // stats entry stride
#define PART_ENTRIES (32 * PSTRIDE)   // 1056

// Scratch (static device arrays; no runtime allocation allowed)
__device__ float g_L[(size_t)M_TOT * 1024];        // Cholesky factors, COLUMN-major per matrix
__device__ float g_part[PART_ENTRIES * BLOCKS];    // per-block partials, [entry][block]
__device__ float g_sums[PART_ENTRIES];
__device__ float g_stats[1025];                    // mean[32*32] (diag slot = logd mean) + factor

// ---------------------------------------------------------------------------
// Pass 1: coalesced load + smem transpose, warp-per-matrix Cholesky with
// shared-memory column broadcasts (float4), direct coalesced column-major
// store of L (in-loop, overlapped), Log-Cholesky statistic accumulation.
// (Unchanged from R12 — measured fast.)
// ---------------------------------------------------------------------------
__global__ void __launch_bounds__(THREADS) chol_pass1(const float* __restrict__ X) {
    __shared__ float4 sbuf[WPB * 304];   // per warp: 288 tile f4 + 16 colbuf f4
    const int lane = threadIdx.x & 31;
    const int wl   = threadIdx.x >> 5;
    float4* tile = sbuf + wl * 304;
    float*  colf = (float*)(tile + 288);
    const int gw = blockIdx.x * WPB + wl;

    float acc[32];
#pragma unroll
    for (int j = 0; j < 32; j++) acc[j] = 0.f;
    float accsq = 0.f;

    for (int m = gw; m < M_TOT; m += NWARPS) {
        // coalesced load of X, transpose through smem (row-major tile)
        const float4* xs = (const float4*)(X + (size_t)m * 1024);
#pragma unroll
        for (int q = 0; q < 8; q++) {
            float4 v = xs[q * 32 + lane];
            tile[(4 * q + (lane >> 3)) * TS4 + (lane & 7)] = v;
        }
        __syncwarp();
        // own row into registers (conflict-free LDS.128)
        float a[32];
#pragma unroll
        for (int q = 0; q < 8; q++) {
            float4 v = tile[lane * TS4 + q];
            a[4*q+0] = v.x; a[4*q+1] = v.y; a[4*q+2] = v.z; a[4*q+3] = v.w;
        }

        float* gl = g_L + (size_t)m * 1024;
        float mydiag = 1.f;
#pragma unroll
        for (int k = 0; k < 32; k++) {
            float akk  = __shfl_sync(0xffffffffu, a[k], k);
            float rinv = rsqrtf(akk);
            float lik  = a[k] * rinv;           // lane==k -> sqrt(akk)
            if (lane < k) lik = 0.f;
            if (lane == k) mydiag = lik;
            a[k] = lik;
            gl[k * 32 + lane] = lik;            // coalesced column-major store of L
            float* cb = colf + ((k & 1) << 5);  // double-buffered column broadcast
            cb[lane] = lik;
            __syncwarp();
            // rank-1 update via broadcast float4 reads of column k
#pragma unroll
            for (int q = (k + 1) / 4; q < 8; q++) {
                float4 c = ((const float4*)cb)[q];
                if (4*q+0 > k) a[4*q+0] -= lik * c.x;
                if (4*q+1 > k) a[4*q+1] -= lik * c.y;
                if (4*q+2 > k) a[4*q+2] -= lik * c.z;
                if (4*q+3 > k) a[4*q+3] -= lik * c.w;
            }
        }
        float logd = __logf(mydiag);

        // accumulate Log-Cholesky coords (strict lower + logd in diag slot)
#pragma unroll
        for (int j = 0; j < 32; j++) {
            float v = (j < lane) ? a[j] : ((j == lane) ? logd : 0.f);
            acc[j] += v;
            accsq  += v * v;
        }
    }

    // block reduction: reuse sbuf as sred (tiles dead now)
    __syncthreads();
    float* sred = (float*)sbuf;   // WPB*PART_ENTRIES floats fits in sbuf
#pragma unroll
    for (int j = 0; j < 32; j++)
        sred[wl * PART_ENTRIES + lane * PSTRIDE + j] = acc[j];
    sred[wl * PART_ENTRIES + lane * PSTRIDE + 32] = accsq;
    __syncthreads();

    for (int e = threadIdx.x; e < PART_ENTRIES; e += THREADS) {
        float s = 0.f;
#pragma unroll
        for (int w = 0; w < WPB; w++) s += sred[w * PART_ENTRIES + e];
        g_part[e * BLOCKS + blockIdx.x] = s;   // [entry][block] -> coalesced reduce
    }
}

// ---------------------------------------------------------------------------
// k2a: deterministic tree reduction of 1024 block partials per entry (coalesced).
// ---------------------------------------------------------------------------
__global__ void reduce2a() {
    __shared__ float red[BLOCKS];
    const int e = blockIdx.x;
    red[threadIdx.x] = g_part[e * BLOCKS + threadIdx.x];
    __syncthreads();
#pragma unroll
    for (int s = BLOCKS / 2; s > 0; s >>= 1) {
        if ((int)threadIdx.x < s) red[threadIdx.x] += red[threadIdx.x + s];
        __syncthreads();
    }
    if (threadIdx.x == 0) g_sums[e] = red[0];
}

// ---------------------------------------------------------------------------
// k2b: means, variance = E||x||^2 - ||Ex||^2, factor = s / sqrt(var).
// ---------------------------------------------------------------------------
__global__ void stats_pass(const float* __restrict__ s_in) {
    __shared__ float red[1024];
    const int t = threadIdx.x;               // 1024 threads
    const int i = t >> 5, j = t & 31;
    const float invM = 1.0f / (float)M_TOT;

    float mean = g_sums[i * PSTRIDE + j] * invM;   // 0 for strictly-upper slots
    g_stats[i * 32 + j] = mean;
    float val = -mean * mean;
    if (t < 32) val += g_sums[t * PSTRIDE + 32] * invM;
    red[t] = val;
    __syncthreads();
#pragma unroll
    for (int s = 512; s > 0; s >>= 1) {
        if (t < s) red[t] += red[t + s];
        __syncthreads();
    }
    if (t == 0) {
        float var = red[0];
        g_stats[1024] = s_in[0] / sqrtf(var);
    }
}

// ---------------------------------------------------------------------------
// Pass 3: coalesced column-major load of L into smem, center + geodesic
// rescale, L_out L_out^T with float4 broadcast reads (k outer, j vectorized),
// coalesced store through smem staging. Mean stored COLUMN-major (stride 33)
// so the b-loop mean read is stride-1 across lanes (was a 4-way conflict).
// ---------------------------------------------------------------------------
__global__ void __launch_bounds__(THREADS) out_pass(float* __restrict__ out) {
    __shared__ float4 sbuf[WPB * 288];       // tiles
    __shared__ float  smean_cm[32 * 33];     // mean, column-major: [j*33 + i]
    __shared__ float  smean_d[32];           // logd means
    __shared__ float  sfac;

    for (int e = threadIdx.x; e < 1024; e += THREADS) {
        int i = e >> 5, j = e & 31;
        float v = g_stats[e];
        smean_cm[j * 33 + i] = (i == j) ? 0.f : v;   // diag handled separately
        if (i == j) smean_d[i] = v;
    }
    if (threadIdx.x == 0) sfac = g_stats[1024];
    __syncthreads();
    const float factor = sfac;

    const int lane = threadIdx.x & 31;
    const int wl   = threadIdx.x >> 5;
    float4* tile = sbuf + wl * 288;
    float*  tf   = (float*)tile;
    const int gw = blockIdx.x * WPB + wl;

    for (int m = gw; m < M_TOT; m += NWARPS) {
        // coalesced load of column-major L -> column-major smem tile tf[col*TS + row]
        const float4* ls = (const float4*)(g_L + (size_t)m * 1024);
#pragma unroll
        for (int q = 0; q < 8; q++) {
            float4 v = ls[q * 32 + lane];    // col 4q+lane/8, rows 4(lane&7)..+3
            tile[(4 * q + (lane >> 3)) * TS4 + (lane & 7)] = v;
        }
        __syncwarp();

        // centered / rescaled own row b (lane i = row i). Upper entries are 0
        // automatically (L upper zeros, mean strict-upper zeros).
        float dL    = tf[lane * TS + lane];          // L[i][i]  (stride-37: conflict-free)
        float mdiag = smean_d[lane];                 // logd mean (stride-1)
        float edc   = __expf(factor * (__logf(dL) - mdiag));
        float b[32];
#pragma unroll
        for (int j = 0; j < 32; j++) {
            float aj = tf[j * TS + lane];            // L[i][j]      (stride-1: conflict-free)
            float mj = smean_cm[j * 33 + lane];      // mean[i][j]   (stride-1: conflict-free)
            float v  = factor * (aj - mj);
            b[j] = (j == lane) ? edc : v;
        }
        // write b back into own column-major slots (only lane i touches (j,i))
#pragma unroll
        for (int j = 0; j < 32; j++) tf[j * TS + lane] = b[j];
        __syncwarp();

        // X_out row i: o[j] = sum_k b_i[k] * b_j[k]; k outer, j chunks of 4
        // (broadcast LDS.128 of column k = {b_j[k]}_j). b[k]=0 for k>lane
        // truncates the row; tile zeros truncate j<k.
        float o[32];
#pragma unroll
        for (int j = 0; j < 32; j++) o[j] = 0.f;
#pragma unroll
        for (int k = 0; k < 32; k++) {
            float bk = b[k];
#pragma unroll
            for (int q = k / 4; q < 8; q++) {
                float4 c = tile[k * TS4 + q];        // b_{4q..4q+3}[k], broadcast
                if (4*q+0 >= k) o[4*q+0] += bk * c.x;
                if (4*q+1 >= k) o[4*q+1] += bk * c.y;
                if (4*q+2 >= k) o[4*q+2] += bk * c.z;
                if (4*q+3 >= k) o[4*q+3] += bk * c.w;
            }
        }
        __syncwarp();   // all tile reads done before restage

        // stage o row-major, then coalesced store
#pragma unroll
        for (int q = 0; q < 8; q++)
            tile[lane * TS4 + q] = make_float4(o[4*q], o[4*q+1], o[4*q+2], o[4*q+3]);
        __syncwarp();
        float4* od = (float4*)(out + (size_t)m * 1024);
#pragma unroll
        for (int q = 0; q < 8; q++)
            od[q * 32 + lane] = tile[(4 * q + (lane >> 3)) * TS4 + (lane & 7)];
        __syncwarp();
    }
}

extern "C" void kernel_launch(void* const* d_in, const int* in_sizes, int n_in,
                              void* d_out, int out_size) {
    const float* X = (const float*)d_in[0];
    const float* s = (const float*)d_in[1];
    float* out = (float*)d_out;

    chol_pass1<<<BLOCKS, THREADS>>>(X);
    reduce2a<<<PART_ENTRIES, BLOCKS>>>();
    stats_pass<<<1, 1024>>>(s);
    out_pass<<<BLOCKS, THREADS>>>(out);
}

// round 14
// speedup vs baseline: 1.4113x; 1.0084x over previous
#include <cuda_runtime.h>
#include <math.h>

// Problem constants
#define M_TOT 32768            // 512*64 matrices
#define BLOCKS 1024
#define THREADS 128
#define WPB 4
#define NWARPS (BLOCKS * WPB)  // 4096 warps -> 8 matrices each
#define TS 36                  // tile row stride in floats (16B-aligned, conflict-free)
#define TS4 9                  // tile row stride in float4
#define PSTRIDE 33             // stats entry stride
#define PART_ENTRIES (32 * PSTRIDE)   // 1056

// Scratch (static device arrays; no runtime allocation allowed)
__device__ float g_L[(size_t)M_TOT * 1024];        // Cholesky factors, COLUMN-major per matrix
__device__ float g_part[PART_ENTRIES * BLOCKS];    // per-block partials, [entry][block]
__device__ float g_sums[PART_ENTRIES];
__device__ float g_stats[1025];                    // mean[32*32] (diag slot = logd mean) + factor

// ---------------------------------------------------------------------------
// Pass 1: coalesced load + smem transpose, warp-per-matrix Cholesky with
// DEFERRED NORMALIZATION: the raw updated column is broadcast through smem
// (no shfl, no rsqrt on the critical path); rank-1 update uses
// raw_i * raw_j / akk. Normalized lik computed off-path for store + stats.
// ---------------------------------------------------------------------------
__global__ void __launch_bounds__(THREADS) chol_pass1(const float* __restrict__ X) {
    __shared__ float4 sbuf[WPB * 304];   // per warp: 288 tile f4 + 16 colbuf f4
    const int lane = threadIdx.x & 31;
    const int wl   = threadIdx.x >> 5;
    float4* tile = sbuf + wl * 304;
    float*  colf = (float*)(tile + 288);
    const int gw = blockIdx.x * WPB + wl;

    float acc[32];
#pragma unroll
    for (int j = 0; j < 32; j++) acc[j] = 0.f;
    float accsq = 0.f;

    for (int m = gw; m < M_TOT; m += NWARPS) {
        // coalesced load of X, transpose through smem (row-major tile)
        const float4* xs = (const float4*)(X + (size_t)m * 1024);
#pragma unroll
        for (int q = 0; q < 8; q++) {
            float4 v = xs[q * 32 + lane];
            tile[(4 * q + (lane >> 3)) * TS4 + (lane & 7)] = v;
        }
        __syncwarp();
        // own row into registers (conflict-free LDS.128)
        float a[32];
#pragma unroll
        for (int q = 0; q < 8; q++) {
            float4 v = tile[lane * TS4 + q];
            a[4*q+0] = v.x; a[4*q+1] = v.y; a[4*q+2] = v.z; a[4*q+3] = v.w;
        }

        float* gl = g_L + (size_t)m * 1024;
        float mydiag = 1.f;
#pragma unroll
        for (int k = 0; k < 32; k++) {
            float araw = a[k];                  // raw updated column entry (this lane)
            float* cb = colf + ((k & 1) << 5);  // double-buffered column broadcast
            cb[lane] = araw;                    // STS first -> shortest critical path
            __syncwarp();
            float akk  = cb[k];                 // broadcast scalar LDS (lane k's raw diag)
            float t    = __fdividef(araw, akk); // raw/akk for deferred-normalized update
            float rinv = rsqrtf(akk);           // off critical path
            float lik  = araw * rinv;           // normalized entry; lane==k -> sqrt(akk)
            if (lane < k) lik = 0.f;
            if (lane == k) mydiag = lik;
            a[k] = lik;
            gl[k * 32 + lane] = lik;            // coalesced column-major store of L
            // rank-1 update: a[j] -= t * raw_j  (== l_ik * l_jk). Lanes < k do
            // harmless garbage updates on entries that are dead (overwritten by
            // the zeroed lik at their own iteration before any use).
#pragma unroll
            for (int q = (k + 1) / 4; q < 8; q++) {
                float4 c = ((const float4*)cb)[q];
                if (4*q+0 > k) a[4*q+0] -= t * c.x;
                if (4*q+1 > k) a[4*q+1] -= t * c.y;
                if (4*q+2 > k) a[4*q+2] -= t * c.z;
                if (4*q+3 > k) a[4*q+3] -= t * c.w;
            }
        }
        float logd = __logf(mydiag);

        // accumulate Log-Cholesky coords (strict lower + logd in diag slot)
#pragma unroll
        for (int j = 0; j < 32; j++) {
            float v = (j < lane) ? a[j] : ((j == lane) ? logd : 0.f);
            acc[j] += v;
            accsq  += v * v;
        }
    }

    // block reduction: reuse sbuf as sred (tiles dead now)
    __syncthreads();
    float* sred = (float*)sbuf;   // WPB*PART_ENTRIES floats fits in sbuf
#pragma unroll
    for (int j = 0; j < 32; j++)
        sred[wl * PART_ENTRIES + lane * PSTRIDE + j] = acc[j];
    sred[wl * PART_ENTRIES + lane * PSTRIDE + 32] = accsq;
    __syncthreads();

    for (int e = threadIdx.x; e < PART_ENTRIES; e += THREADS) {
        float s = 0.f;
#pragma unroll
        for (int w = 0; w < WPB; w++) s += sred[w * PART_ENTRIES + e];
        g_part[e * BLOCKS + blockIdx.x] = s;   // [entry][block] -> coalesced reduce
    }
}

// ---------------------------------------------------------------------------
// k2a: deterministic tree reduction of 1024 block partials per entry (coalesced).
// ---------------------------------------------------------------------------
__global__ void reduce2a() {
    __shared__ float red[BLOCKS];
    const int e = blockIdx.x;
    red[threadIdx.x] = g_part[e * BLOCKS + threadIdx.x];
    __syncthreads();
#pragma unroll
    for (int s = BLOCKS / 2; s > 0; s >>= 1) {
        if ((int)threadIdx.x < s) red[threadIdx.x] += red[threadIdx.x + s];
        __syncthreads();
    }
    if (threadIdx.x == 0) g_sums[e] = red[0];
}

// ---------------------------------------------------------------------------
// k2b: means, variance = E||x||^2 - ||Ex||^2, factor = s / sqrt(var).
// ---------------------------------------------------------------------------
__global__ void stats_pass(const float* __restrict__ s_in) {
    __shared__ float red[1024];
    const int t = threadIdx.x;               // 1024 threads
    const int i = t >> 5, j = t & 31;
    const float invM = 1.0f / (float)M_TOT;

    float mean = g_sums[i * PSTRIDE + j] * invM;   // 0 for strictly-upper slots
    g_stats[i * 32 + j] = mean;
    float val = -mean * mean;
    if (t < 32) val += g_sums[t * PSTRIDE + 32] * invM;
    red[t] = val;
    __syncthreads();
#pragma unroll
    for (int s = 512; s > 0; s >>= 1) {
        if (t < s) red[t] += red[t + s];
        __syncthreads();
    }
    if (t == 0) {
        float var = red[0];
        g_stats[1024] = s_in[0] / sqrtf(var);
    }
}

// ---------------------------------------------------------------------------
// Pass 3: coalesced column-major load of L into smem, center + geodesic
// rescale, L_out L_out^T with float4 broadcast reads (k outer, j vectorized),
// coalesced store through smem staging. Mean stored COLUMN-major (stride 33)
// so the b-loop mean read is stride-1 across lanes. (Unchanged from R13.)
// ---------------------------------------------------------------------------
__global__ void __launch_bounds__(THREADS) out_pass(float* __restrict__ out) {
    __shared__ float4 sbuf[WPB * 288];       // tiles
    __shared__ float  smean_cm[32 * 33];     // mean, column-major: [j*33 + i]
    __shared__ float  smean_d[32];           // logd means
    __shared__ float  sfac;

    for (int e = threadIdx.x; e < 1024; e += THREADS) {
        int i = e >> 5, j = e & 31;
        float v = g_stats[e];
        smean_cm[j * 33 + i] = (i == j) ? 0.f : v;   // diag handled separately
        if (i == j) smean_d[i] = v;
    }
    if (threadIdx.x == 0) sfac = g_stats[1024];
    __syncthreads();
    const float factor = sfac;

    const int lane = threadIdx.x & 31;
    const int wl   = threadIdx.x >> 5;
    float4* tile = sbuf + wl * 288;
    float*  tf   = (float*)tile;
    const int gw = blockIdx.x * WPB + wl;

    for (int m = gw; m < M_TOT; m += NWARPS) {
        // coalesced load of column-major L -> column-major smem tile tf[col*TS + row]
        const float4* ls = (const float4*)(g_L + (size_t)m * 1024);
#pragma unroll
        for (int q = 0; q < 8; q++) {
            float4 v = ls[q * 32 + lane];    // col 4q+lane/8, rows 4(lane&7)..+3
            tile[(4 * q + (lane >> 3)) * TS4 + (lane & 7)] = v;
        }
        __syncwarp();

        // centered / rescaled own row b (lane i = row i). Upper entries are 0
        // automatically (L upper zeros, mean strict-upper zeros).
        float dL    = tf[lane * TS + lane];          // L[i][i]  (stride-37: conflict-free)
        float mdiag = smean_d[lane];                 // logd mean (stride-1)
        float edc   = __expf(factor * (__logf(dL) - mdiag));
        float b[32];
#pragma unroll
        for (int j = 0; j < 32; j++) {
            float aj = tf[j * TS + lane];            // L[i][j]      (stride-1: conflict-free)
            float mj = smean_cm[j * 33 + lane];      // mean[i][j]   (stride-1: conflict-free)
            float v  = factor * (aj - mj);
            b[j] = (j == lane) ? edc : v;
        }
        // write b back into own column-major slots (only lane i touches (j,i))
#pragma unroll
        for (int j = 0; j < 32; j++) tf[j * TS + lane] = b[j];
        __syncwarp();

        // X_out row i: o[j] = sum_k b_i[k] * b_j[k]; k outer, j chunks of 4
        // (broadcast LDS.128 of column k = {b_j[k]}_j). b[k]=0 for k>lane
        // truncates the row; tile zeros truncate j<k.
        float o[32];
#pragma unroll
        for (int j = 0; j < 32; j++) o[j] = 0.f;
#pragma unroll
        for (int k = 0; k < 32; k++) {
            float bk = b[k];
#pragma unroll
            for (int q = k / 4; q < 8; q++) {
                float4 c = tile[k * TS4 + q];        // b_{4q..4q+3}[k], broadcast
                if (4*q+0 >= k) o[4*q+0] += bk * c.x;
                if (4*q+1 >= k) o[4*q+1] += bk * c.y;
                if (4*q+2 >= k) o[4*q+2] += bk * c.z;
                if (4*q+3 >= k) o[4*q+3] += bk * c.w;
            }
        }
        __syncwarp();   // all tile reads done before restage

        // stage o row-major, then coalesced store
#pragma unroll
        for (int q = 0; q < 8; q++)
            tile[lane * TS4 + q] = make_float4(o[4*q], o[4*q+1], o[4*q+2], o[4*q+3]);
        __syncwarp();
        float4* od = (float4*)(out + (size_t)m * 1024);
#pragma unroll
        for (int q = 0; q < 8; q++)
            od[q * 32 + lane] = tile[(4 * q + (lane >> 3)) * TS4 + (lane & 7)];
        __syncwarp();
    }
}

extern "C" void kernel_launch(void* const* d_in, const int* in_sizes, int n_in,
                              void* d_out, int out_size) {
    const float* X = (const float*)d_in[0];
    const float* s = (const float*)d_in[1];
    float* out = (float*)d_out;

    chol_pass1<<<BLOCKS, THREADS>>>(X);
    reduce2a<<<PART_ENTRIES, BLOCKS>>>();
    stats_pass<<<1, 1024>>>(s);
    out_pass<<<BLOCKS, THREADS>>>(out);
}